// round 14
// baseline (speedup 1.0000x reference)
#include <cuda_runtime.h>
#include <math.h>

#define EMAX 4096
#define NB2  256
#define W    8
#define CAPW (EMAX*EMAX/2 + EMAX)     /* one-sided window-slot buffer */
#define PI_F   3.14159274101257324f
#define THR_F  0.08726646259971647f
#define BSCALE 81.48733086305042f     /* 256/pi */
#define INF_BITS 0x7F800000u
#define GRID 256
#define NTHR 512

// ---- device scratch (no allocations allowed) ----
__device__ float4   g_i4[EMAX];        // (ang, nx, ny, c) by original edge idx
__device__ float2   g_mid[EMAX];
__device__ int      g_bine[EMAX];
__device__ unsigned g_bcnt[NB2], g_bcur[NB2];
__device__ unsigned g_T;               // total one-sided slots
__device__ float4   g_q4[EMAX];        // bucket-order: (ang, mx, my, bitcast(orig idx))
__device__ float4   g_l4[EMAX];        // bucket-order: (nx, ny, c, unused)
__device__ __align__(16) float g_bufw[CAPW];  // window slots: dist or +inf
__device__ unsigned g_hA[2048];        // float bits [21..31]
__device__ unsigned g_hB[3 * 2048];    // bits [10..20] per rank
__device__ unsigned g_hC[3 * 1024];    // bits [0..9]  per rank
__device__ unsigned g_n;
__device__ unsigned g_pA[3], g_rA[3];
__device__ unsigned g_pB[3], g_rB[3];
__device__ unsigned g_done;
__device__ double   g_sum;
// monotone grid-barrier state (never reset; replay-safe)
__device__ unsigned g_arrive_v;
__device__ unsigned g_sense_v;

// ---------------------------------------------------------------------------
__device__ __forceinline__ void gsync(unsigned base, unsigned& bidx)
{
    __syncthreads();
    if (threadIdx.x == 0) {
        unsigned target = base + (++bidx);
        __threadfence();
        unsigned old = atomicAdd(&g_arrive_v, 1u);
        if (old + 1u == target * GRID) {
            __threadfence();
            *(volatile unsigned*)&g_sense_v = target;
        } else {
            while ((int)(*(volatile unsigned*)&g_sense_v - target) < 0)
                __nanosleep(64);
        }
        __threadfence();
    }
    __syncthreads();
}

// Shuffle-based inclusive block scan over 512 threads (3 barriers).
// All threads must call; returns inclusive prefix; *total = block total.
__device__ __forceinline__ unsigned bscan(unsigned v, unsigned* ws, unsigned* total)
{
    int lane = threadIdx.x & 31, w = threadIdx.x >> 5;
    #pragma unroll
    for (int o = 1; o < 32; o <<= 1) {
        unsigned x = __shfl_up_sync(0xFFFFFFFFu, v, o);
        if (lane >= o) v += x;
    }
    if (lane == 31) ws[w] = v;
    __syncthreads();
    if (w == 0) {
        unsigned s = (lane < 16) ? ws[lane] : 0u;
        #pragma unroll
        for (int o = 1; o < 16; o <<= 1) {
            unsigned x = __shfl_up_sync(0xFFFFFFFFu, s, o);
            if (lane >= o) s += x;
        }
        if (lane < 16) ws[lane] = s;
    }
    __syncthreads();
    unsigned basep = (w > 0) ? ws[w - 1] : 0u;
    unsigned tot   = ws[15];
    __syncthreads();
    *total = tot;
    return v + basep;
}

// ---------------------------------------------------------------------------
// K1 (FUSED PREP): zero+geometry | gsync | redundant scans + scatter | gsync
//     | one-sided enumeration.  <<<GRID,512>>>
// ---------------------------------------------------------------------------
__global__ void __launch_bounds__(512) k_prep(const float* __restrict__ pos,
                                             const int* __restrict__ eidx, int E)
{
    __shared__ unsigned sb[NB2 + 1];   // bucket offsets (exclusive) + total
    __shared__ unsigned sB[NB2 + 1];   // one-sided slot bases + total
    __shared__ unsigned sh[2048];      // level-A histogram
    __shared__ unsigned ws[16];
    __shared__ unsigned s_sense;
    const int t    = threadIdx.x;
    const int gtid = blockIdx.x * NTHR + t;
    const int nt   = GRID * NTHR;

    if (t == 0) s_sense = *(volatile unsigned*)&g_sense_v;
    __syncthreads();
    const unsigned base = s_sense;
    unsigned bidx = 0;

    // ---- P0: zero scratch + per-edge geometry + bucket counts ----
    for (int k = gtid; k < 2048;   k += nt) g_hA[k] = 0u;
    for (int k = gtid; k < 3*2048; k += nt) g_hB[k] = 0u;
    for (int k = gtid; k < 3*1024; k += nt) g_hC[k] = 0u;
    if (gtid < NB2) { g_bcnt[gtid] = 0u; g_bcur[gtid] = 0u; }
    if (gtid == 0)  { g_sum = 0.0; g_done = 0u; g_n = 0u; }

    if (gtid < E) {
        int e = gtid;
        int s = eidx[e];
        int d = eidx[E + e];
        float sx = pos[2*s], sy = pos[2*s+1];
        float dx = pos[2*d], dy = pos[2*d+1];
        float vx = dx - sx, vy = dy - sy;
        float len = fmaxf(sqrtf(vx*vx + vy*vy), 1e-8f);
        float ux = vx / len, uy = vy / len;
        float a = atan2f(uy, ux);
        a = fmodf(a, PI_F);
        if (a < 0.f) a += PI_F;
        float nx = -uy, ny = ux;
        g_i4[e]  = make_float4(a, nx, ny, sx*nx + sy*ny);
        g_mid[e] = make_float2((sx + dx) * 0.5f, (sy + dy) * 0.5f);
        int b = (int)(a * BSCALE);
        if (b >= NB2) b = NB2 - 1;
        if (b < 0)    b = 0;
        g_bine[e] = b;
        atomicAdd(&g_bcnt[b], 1u);
    }
    gsync(base, bidx);                                     // B1

    // ---- P1: redundant per-block scans (shared-resident) + scatter ----
    {
        unsigned c = (t < NB2) ? g_bcnt[t] : 0u;
        unsigned tot;
        unsigned inc = bscan(c, ws, &tot);
        unsigned exc = inc - c;
        if (t < NB2) sb[t] = exc;
        if (t == 0)  sb[NB2] = tot;
        __syncthreads();

        unsigned S = 0;
        if (t < NB2) {
            unsigned o = sb[t];
            unsigned U = sb[(t + 9 <= NB2) ? (t + 9) : NB2];
            unsigned X = (t <= 7) ? (sb[NB2] - sb[t + 248]) : 0u;
            S = c * (U - 1u + X) - c * o - (c * (c - 1u)) / 2u;
        }
        unsigned totS;
        unsigned incS = bscan(S, ws, &totS);
        if (t < NB2) sB[t] = incS - S;
        if (t == 0)  { sB[NB2] = totS; g_T = totS; }      // identical across blocks
        __syncthreads();

        if (gtid < E) {
            int b = g_bine[gtid];
            unsigned slot = sb[b] + atomicAdd(&g_bcur[b], 1u);
            float4 f = g_i4[gtid];
            float2 m = g_mid[gtid];
            g_q4[slot] = make_float4(f.x, m.x, m.y, __int_as_float(gtid));
            g_l4[slot] = make_float4(f.y, f.z, f.w, 0.f);
        }
        for (int k = t; k < 2048; k += NTHR) sh[k] = 0u;  // zero level-A hist
    }
    gsync(base, bidx);                                     // B2

    // ---- P2: one-sided enumeration (1 warp per slot) ----
    {
        int gw   = gtid >> 5;
        int lane = t & 31;
        int nw   = nt >> 5;

        for (int s = gw; s < E; s += nw) {
            float4 qs = g_q4[s];
            int u = __float_as_int(qs.w);
            float au = qs.x, mxu = qs.y, myu = qs.z;
            float4 lu = g_l4[s];
            float nxu = lu.x, nyu = lu.y, cu = lu.z;
            int b = g_bine[u];

            int o = (int)sb[b];
            int U = (int)sb[(b + 9 <= NB2) ? (b + 9) : NB2];
            int X = (b <= 7) ? (int)(sb[NB2] - sb[b + 248]) : 0;

            int so = s - o;
            unsigned obase = sB[b] + (unsigned)(so * (U - 1 + X)) - (unsigned)(((o + s - 1) * so) / 2);
            int cnt_f = U - s - 1;

            for (int k = s + 1 + lane; k < U; k += 32) {
                float4 q = g_q4[k];
                float da   = fabsf(au - q.x);
                float circ = fminf(da, PI_F - da);
                float val  = __uint_as_float(INF_BITS);
                if (circ <= THR_F) {                     // exact reference mask
                    int ov = __float_as_int(q.w);
                    if (u < ov) {
                        val = fabsf(fmaf(nxu, q.y, fmaf(nyu, q.z, -cu)));
                    } else {
                        float4 lv = g_l4[k];
                        val = fabsf(fmaf(lv.x, mxu, fmaf(lv.y, myu, -lv.z)));
                    }
                    atomicAdd(&sh[__float_as_uint(val) >> 21], 1u);
                }
                g_bufw[obase + (unsigned)(k - s - 1)] = val;
            }
            if (X > 0) {
                int wsrt = (int)sb[b + 248];
                int wend = (int)sb[NB2];
                for (int k = wsrt + lane; k < wend; k += 32) {
                    float4 q = g_q4[k];
                    float da   = fabsf(au - q.x);
                    float circ = fminf(da, PI_F - da);
                    float val  = __uint_as_float(INF_BITS);
                    if (circ <= THR_F) {
                        int ov = __float_as_int(q.w);
                        if (u < ov) {
                            val = fabsf(fmaf(nxu, q.y, fmaf(nyu, q.z, -cu)));
                        } else {
                            float4 lv = g_l4[k];
                            val = fabsf(fmaf(lv.x, mxu, fmaf(lv.y, myu, -lv.z)));
                        }
                        atomicAdd(&sh[__float_as_uint(val) >> 21], 1u);
                    }
                    g_bufw[obase + (unsigned)(cnt_f + (k - wsrt))] = val;
                }
            }
        }
        __syncthreads();
        for (int k = t; k < 2048; k += NTHR) {
            unsigned v = sh[k];
            if (v) atomicAdd(&g_hA[k], v);
        }
    }
}

// ---------------------------------------------------------------------------
// K2 (FUSED SELECT): pickA + histB | gsync | pickB + histC | gsync |
//     pickC + loss + finalize.  <<<GRID,512>>>  (shuffle scans throughout)
// ---------------------------------------------------------------------------
__global__ void __launch_bounds__(512) k_select_loss(float* __restrict__ out)
{
    __shared__ unsigned ws[16];
    __shared__ unsigned sp[3];
    __shared__ float    sq[3];
    __shared__ unsigned s_sense;
    int t = threadIdx.x;
    if (t == 0) s_sense = *(volatile unsigned*)&g_sense_v;
    if (t < 3) { sp[t] = 0xFFFFFFFFu; sq[t] = 0.f; }
    __syncthreads();
    const unsigned sbase = s_sense;
    unsigned bidx = 0;

    const unsigned T  = g_T;
    const unsigned T4 = T >> 2;
    const float4* buf4 = (const float4*)g_bufw;
    const unsigned stride = GRID * NTHR;
    const unsigned gt = blockIdx.x * NTHR + t;

    // ---------------- phase 1: pickA + histB ----------------
    unsigned n;
    {
        unsigned loc[4], s = 0;
        #pragma unroll
        for (int k = 0; k < 4; k++) { loc[k] = g_hA[t*4 + k]; s += loc[k]; }
        unsigned inc = bscan(s, ws, &n);
        unsigned exc = inc - s;
        if (t == 0) g_n = n;

        if (n) {
            unsigned r[3];
            r[0] = (n/4 > 0u) ? (n/4 - 1u) : 0u;
            r[1] = n/2;
            unsigned q3i = (unsigned)((3ull * n) / 4ull);
            if (q3i > n - 1u) q3i = n - 1u;
            r[2] = q3i;
            #pragma unroll
            for (int st = 0; st < 3; st++) {
                if (s && exc <= r[st] && r[st] < inc) {
                    unsigned cum = exc;
                    #pragma unroll
                    for (int k = 0; k < 4; k++) {
                        if (cum + loc[k] > r[st]) {
                            sp[st] = (unsigned)(t*4 + k);
                            g_pA[st] = sp[st];
                            g_rA[st] = r[st] - cum;
                            break;
                        }
                        cum += loc[k];
                    }
                }
            }
        }
        __syncthreads();

        if (n) {
            unsigned p0 = sp[0], p1 = sp[1], p2 = sp[2];
            for (unsigned i4 = gt; i4 < T4; i4 += stride) {
                float4 v4 = buf4[i4];
                #pragma unroll
                for (int c = 0; c < 4; c++) {
                    unsigned bits = __float_as_uint(c == 0 ? v4.x : c == 1 ? v4.y : c == 2 ? v4.z : v4.w);
                    unsigned a11 = bits >> 21, m11 = (bits >> 10) & 2047u;
                    if (a11 == p0) atomicAdd(&g_hB[m11],        1u);
                    if (a11 == p1) atomicAdd(&g_hB[2048 + m11], 1u);
                    if (a11 == p2) atomicAdd(&g_hB[4096 + m11], 1u);
                }
            }
            for (unsigned idx = (T4 << 2) + gt; idx < T; idx += stride) {
                unsigned bits = __float_as_uint(g_bufw[idx]);
                unsigned a11 = bits >> 21, m11 = (bits >> 10) & 2047u;
                if (a11 == p0) atomicAdd(&g_hB[m11],        1u);
                if (a11 == p1) atomicAdd(&g_hB[2048 + m11], 1u);
                if (a11 == p2) atomicAdd(&g_hB[4096 + m11], 1u);
            }
        }
    }
    gsync(sbase, bidx);                                    // B1

    // ---------------- phase 2: pickB + histC ----------------
    {
        __shared__ unsigned spf[3];
        if (t < 3) spf[t] = 0xFFFFFFFFu;
        if (n) {
            for (int st = 0; st < 3; st++) {
                unsigned rA = g_rA[st];
                unsigned pA = g_pA[st];
                unsigned loc[4], s = 0;
                #pragma unroll
                for (int k = 0; k < 4; k++) { loc[k] = g_hB[st*2048 + t*4 + k]; s += loc[k]; }
                unsigned tot;
                unsigned inc = bscan(s, ws, &tot);
                unsigned exc = inc - s;
                if (s && exc <= rA && rA < inc) {
                    unsigned cum = exc;
                    #pragma unroll
                    for (int k = 0; k < 4; k++) {
                        if (cum + loc[k] > rA) {
                            unsigned pb = (unsigned)(t*4 + k);
                            g_pB[st] = pb;
                            g_rB[st] = rA - cum;
                            spf[st]  = (pA << 11) | pb;
                            break;
                        }
                        cum += loc[k];
                    }
                }
                __syncthreads();
            }
            unsigned p0 = spf[0], p1 = spf[1], p2 = spf[2];
            for (unsigned i4 = gt; i4 < T4; i4 += stride) {
                float4 v4 = buf4[i4];
                #pragma unroll
                for (int c = 0; c < 4; c++) {
                    unsigned bits = __float_as_uint(c == 0 ? v4.x : c == 1 ? v4.y : c == 2 ? v4.z : v4.w);
                    unsigned ab22 = bits >> 10, l10 = bits & 1023u;
                    if (ab22 == p0) atomicAdd(&g_hC[l10],        1u);
                    if (ab22 == p1) atomicAdd(&g_hC[1024 + l10], 1u);
                    if (ab22 == p2) atomicAdd(&g_hC[2048 + l10], 1u);
                }
            }
            for (unsigned idx = (T4 << 2) + gt; idx < T; idx += stride) {
                unsigned bits = __float_as_uint(g_bufw[idx]);
                unsigned ab22 = bits >> 10, l10 = bits & 1023u;
                if (ab22 == p0) atomicAdd(&g_hC[l10],        1u);
                if (ab22 == p1) atomicAdd(&g_hC[1024 + l10], 1u);
                if (ab22 == p2) atomicAdd(&g_hC[2048 + l10], 1u);
            }
        }
    }
    gsync(sbase, bidx);                                    // B2

    // ---------------- phase 3: pickC + loss + finalize ----------------
    double acc = 0.0;
    if (n) {
        for (int st = 0; st < 3; st++) {
            unsigned rB = g_rB[st];
            unsigned pA = g_pA[st], pB = g_pB[st];
            unsigned loc[2], s = 0;
            #pragma unroll
            for (int k = 0; k < 2; k++) { loc[k] = g_hC[st*1024 + t*2 + k]; s += loc[k]; }
            unsigned tot;
            unsigned inc = bscan(s, ws, &tot);
            unsigned exc = inc - s;
            if (s && exc <= rB && rB < inc) {
                unsigned cum = exc;
                #pragma unroll
                for (int k = 0; k < 2; k++) {
                    if (cum + loc[k] > rB) {
                        sq[st] = __uint_as_float((pA << 21) | (pB << 10) | (unsigned)(t*2 + k));
                        break;
                    }
                    cum += loc[k];
                }
            }
            __syncthreads();
        }
        float mu = sq[1];
        float margin = fmaxf(sq[2] - sq[0], 1e-6f) * 0.75f;   // iqr * 0.5 * 1.5

        for (unsigned i4 = gt; i4 < T4; i4 += stride) {
            float4 v4 = buf4[i4];
            #pragma unroll
            for (int c = 0; c < 4; c++) {
                float d = (c == 0 ? v4.x : c == 1 ? v4.y : c == 2 ? v4.z : v4.w);
                if (__float_as_uint(d) < INF_BITS) {
                    float h = fabsf(d - mu) - margin;
                    if (h > 0.f) acc += (double)h;
                }
            }
        }
        for (unsigned idx = (T4 << 2) + gt; idx < T; idx += stride) {
            float d = g_bufw[idx];
            if (__float_as_uint(d) < INF_BITS) {
                float h = fabsf(d - mu) - margin;
                if (h > 0.f) acc += (double)h;
            }
        }
    }

    for (int o = 16; o; o >>= 1) acc += __shfl_down_sync(0xFFFFFFFFu, acc, o);
    __shared__ double shs[16];
    if ((t & 31) == 0) shs[t >> 5] = acc;
    __syncthreads();
    if (t < 32) {
        double v = (t < 16) ? shs[t] : 0.0;
        for (int o = 8; o; o >>= 1) v += __shfl_down_sync(0xFFFFFFFFu, v, o);
        if (t == 0 && v != 0.0) atomicAdd(&g_sum, v);
    }
    __shared__ bool last;
    if (t == 0) {
        __threadfence();
        last = (atomicAdd(&g_done, 1u) == gridDim.x - 1);
    }
    __syncthreads();
    if (last && t == 0) {
        __threadfence();
        double denom = (double)(n > 0u ? n : 1u);
        out[0] = (float)(*(volatile double*)&g_sum / denom);
    }
}

// ---------------------------------------------------------------------------
extern "C" void kernel_launch(void* const* d_in, const int* in_sizes, int n_in,
                              void* d_out, int out_size)
{
    const float* pos  = (const float*)d_in[0];   // node_positions (B*N, 2)
    // d_in[1] = adjacency: unused
    const int*   eidx = (const int*)d_in[2];     // edge_index (2, E)
    float* out = (float*)d_out;

    int E = in_sizes[2] / 2;
    if (E > EMAX) E = EMAX;

    k_prep<<<GRID, NTHR>>>(pos, eidx, E);
    k_select_loss<<<GRID, NTHR>>>(out);
}